// round 12
// baseline (speedup 1.0000x reference)
#include <cuda_runtime.h>

// Two-kernel pipeline, all math in packed fma.rn.f32x2:
//  A) corr_kernel: 49-offset wraparound correlation -> g_scratch[49][slots].
//     432 equal-work blocks (256 px x 64 ch), packed accumulator {px0,px1}.
//  B) conv_kernel: 1x1 conv (49->192). Accumulator stays px-packed {px0,px1};
//     weights pre-DUPLICATED in smem as u64 {w,w} so the k-loop is pure
//     LDS.128-broadcast + FFMA2 (no duplication MOVs, no alu traffic).

#define SL 110592   // 65536 (L1) + 2*16384 (L2 parts) + 3*4096 (L3 parts)
__device__ __align__(16) float g_scratch[49 * SL];

__device__ __forceinline__ void cp_async16(void* s, const void* g) {
    unsigned sa = (unsigned)__cvta_generic_to_shared(s);
    asm volatile("cp.async.ca.shared.global [%0], [%1], 16;\n" :: "r"(sa), "l"(g));
}
__device__ __forceinline__ void cp_commit() { asm volatile("cp.async.commit_group;\n" ::: "memory"); }
__device__ __forceinline__ void cp_wait0()  { asm volatile("cp.async.wait_group 0;\n" ::: "memory"); }
__device__ __forceinline__ void cp_wait1()  { asm volatile("cp.async.wait_group 1;\n" ::: "memory"); }

typedef unsigned long long u64;
__device__ __forceinline__ void ffma2(u64& d, u64 a, u64 b) {
    asm("fma.rn.f32x2 %0, %1, %2, %0;" : "+l"(d) : "l"(a), "l"(b));
}
__device__ __forceinline__ u64 add2(u64 a, u64 b) {
    u64 r;
    asm("add.rn.f32x2 %0, %1, %2;" : "=l"(r) : "l"(a), "l"(b));
    return r;
}
__device__ __forceinline__ u64 pk(float lo, float hi) {
    u64 r;
    asm("mov.b64 %0, {%1, %2};" : "=l"(r) : "f"(lo), "f"(hi));
    return r;
}
union U2 { u64 u; float2 f; };

// ---------------- Kernel A: correlation (unchanged from R11) ----------------
#define A_NT 128
#define CC 4
#define F2W 40              // halo row: cols x0-4 .. x0+35 (float4-aligned)
#define F2H 14
#define NOFF (F2H * 10)     // 140 wrapped float4 offsets
#define F1C (CC*8*32)       // 1024 floats
#define F2C (CC*F2H*F2W)    // 2240 floats
#define F2C4 (F2C/4)        // 560 float4
#define ABUF (F1C + F2C)    // 3264
#define NCH (64/CC)         // 16

template<int H, int W>
__device__ __forceinline__ void corr_block(
    const float* __restrict__ f1, const float* __restrict__ f2,
    int x0, int y0, int slot0, float scale, float* sbuf, int* off2s)
{
    const int tid = threadIdx.x;
    const int tx = tid & 15;        // 16 threads * 2px = 32-wide tile
    const int ty = tid >> 4;        // 8 rows
    const int HW = H * W;

    // per-(row, float4) wrapped gmem offsets for the f2 halo. NOFF=140 > 128:
    // strided loop required.
    for (int idx = tid; idx < NOFF; idx += A_NT) {
        int r = idx / 10, q = idx - r * 10;
        int gr = y0 + r - 3;     if (gr < 0) gr += H; if (gr >= H) gr -= H;
        int gc = x0 - 4 + q * 4; if (gc < 0) gc += W; if (gc >= W) gc -= W;
        off2s[idx] = gr * W + gc;
    }
    __syncthreads();

    const float* f1t = f1 + y0 * W + x0;
    auto prefetch = [&](int c0, float* buf) {
#pragma unroll
        for (int j = 0; j < 2; j++) {            // f1: 256 float4
            int idx = tid + j * A_NT;
            int c = idx >> 6, rem = idx & 63;
            int r = rem >> 3, q = rem & 7;
            cp_async16(buf + idx * 4, f1t + (size_t)(c0 + c) * HW + r * W + q * 4);
        }
        float* f2b = buf + F1C;
#pragma unroll
        for (int j = 0; j < 5; j++) {            // f2: 560 float4
            int idx = tid + j * A_NT;
            if (j < 4 || idx < F2C4) {
                int c = idx / 140, rem = idx - c * 140;
                cp_async16(f2b + idx * 4, f2 + (size_t)(c0 + c) * HW + off2s[rem]);
            }
        }
        cp_commit();
    };

    u64 acc[49];
#pragma unroll
    for (int k = 0; k < 49; k++) acc[k] = 0ull;

    prefetch(0, sbuf);
    prefetch(CC, sbuf + ABUF);

#pragma unroll 1
    for (int i = 0; i < NCH; i++) {
        if (i + 1 < NCH) cp_wait1(); else cp_wait0();
        __syncthreads();
        const float* buf = sbuf + (i & 1) * ABUF;
        const float* f1s = buf;
        const float* f2s = buf + F1C;
#pragma unroll
        for (int c = 0; c < CC; c++) {
            const float2 f1v = *(const float2*)&f1s[c * 256 + ty * 32 + 2 * tx];
            const u64 f1p = pk(f1v.x, f1v.y);
            const float* f2c = f2s + c * (F2H * F2W);
#pragma unroll
            for (int iy = 0; iy < 7; iy++) {
                // dy = iy-3 -> halo row ty+6-iy; taps for px pair (2tx+p):
                // halo col j = 2tx + p + 7 - ix  (halo starts at gmem col x0-4)
                const float2* row = (const float2*)(f2c + (ty + 6 - iy) * F2W) + tx;
                float2 e0 = row[0], e1 = row[1], e2 = row[2], e3 = row[3], e4 = row[4];
                const int k0 = iy * 7;
                ffma2(acc[k0 + 0], f1p, pk(e3.y, e4.x));   // {7,8}
                ffma2(acc[k0 + 1], f1p, pk(e3.x, e3.y));   // {6,7}
                ffma2(acc[k0 + 2], f1p, pk(e2.y, e3.x));   // {5,6}
                ffma2(acc[k0 + 3], f1p, pk(e2.x, e2.y));   // {4,5}
                ffma2(acc[k0 + 4], f1p, pk(e1.y, e2.x));   // {3,4}
                ffma2(acc[k0 + 5], f1p, pk(e1.x, e1.y));   // {2,3}
                ffma2(acc[k0 + 6], f1p, pk(e0.y, e1.x));   // {1,2}
            }
        }
        __syncthreads();
        if (i + 2 < NCH) prefetch((i + 2) * CC, sbuf + (i & 1) * ABUF);
    }

    const int slot = slot0 + (y0 + ty) * W + x0 + 2 * tx;
#pragma unroll
    for (int k = 0; k < 49; k++) {
        U2 u; u.u = acc[k];
        float2 v = make_float2(u.f.x * scale, u.f.y * scale);
        *(float2*)&g_scratch[(size_t)k * SL + slot] = v;
    }
}

// 432 equal-work blocks: L1 256 | L2 128 (2 c-parts) | L3 48 (3 c-parts)
__global__ void __launch_bounds__(A_NT, 4)
corr_kernel(const float* __restrict__ l1, const float* __restrict__ l2,
            const float* __restrict__ l3)
{
    __shared__ __align__(16) float sbuf[2 * ABUF];
    __shared__ int off2s[NOFF];
    const int b = blockIdx.x;
    if (b < 256) {
        int img = b >> 6, t = b & 63;                   // 4x16 tiles of 32x8
        int x0 = (t & 3) * 32, y0 = (t >> 2) * 8;
        const float* f1 = l1 + (size_t)img * 64 * 16384;
        const float* f2 = l1 + (size_t)(img + 2) * 64 * 16384;
        corr_block<128, 128>(f1, f2, x0, y0, img * 16384, 0.125f, sbuf, off2s);
    } else if (b < 384) {
        int q = b - 256;
        int img = q >> 5, r = q & 31;
        int part = r >> 4, t = r & 15;                  // 2x8 tiles
        int x0 = (t & 1) * 32, y0 = (t >> 1) * 8;
        const float* f1 = l2 + ((size_t)img * 128 + part * 64) * 4096;
        const float* f2 = l2 + ((size_t)(img + 2) * 128 + part * 64) * 4096;
        corr_block<64, 64>(f1, f2, x0, y0, 65536 + part * 16384 + img * 4096,
                           0.08838834764831845f, sbuf, off2s);
    } else {
        int q = b - 384;
        int img = q / 12, r = q - img * 12;
        int part = r >> 2, t = r & 3;                   // 1x4 tiles
        int y0 = t * 8;
        const float* f1 = l3 + ((size_t)img * 192 + part * 64) * 1024;
        const float* f2 = l3 + ((size_t)(img + 2) * 192 + part * 64) * 1024;
        corr_block<32, 32>(f1, f2, 0, y0, 98304 + part * 4096 + img * 1024,
                           0.07216878364870323f, sbuf, off2s);
    }
}

// ---------------- Kernel B: conv, px-packed acc + dup weights in smem ----------------
#define B_NT 128
// smem (u64): ws2[49*96] dup weights | bias2[96] dup bias  -> 38400 bytes
#define WB_U64 (49 * 96)
#define TOT_U64 (WB_U64 + 96)

template<int HW>
__device__ __forceinline__ void conv_gemm(const u64* __restrict__ corrp,
                                          const u64* __restrict__ ws2,
                                          float* __restrict__ outp)
{
#pragma unroll 1
    for (int pass = 0; pass < 24; pass++) {
        const int d0 = pass * 4;
        ulonglong2 b01 = *(const ulonglong2*)&ws2[WB_U64 + d0];
        ulonglong2 b23 = *(const ulonglong2*)&ws2[WB_U64 + d0 + 2];
        u64 a0 = b01.x, a1 = b01.y, a2 = b23.x, a3 = b23.y;   // {px0,px1} accs
#pragma unroll
        for (int k = 0; k < 49; k++) {
            const u64* wk = &ws2[k * 96 + d0];
            ulonglong2 w01 = *(const ulonglong2*)&wk[0];    // LDS.128 bcast: {w0,w0},{w1,w1}
            ulonglong2 w23 = *(const ulonglong2*)&wk[2];    // LDS.128 bcast: {w2,w2},{w3,w3}
            u64 c = corrp[k];                                // {corr_px0, corr_px1}
            ffma2(a0, c, w01.x);
            ffma2(a1, c, w01.y);
            ffma2(a2, c, w23.x);
            ffma2(a3, c, w23.y);
        }
        U2 u0, u1, u2, u3;
        u0.u = a0; u1.u = a1; u2.u = a2; u3.u = a3;
        *(float2*)&outp[(size_t)(d0 + 0) * HW] = u0.f;
        *(float2*)&outp[(size_t)(d0 + 1) * HW] = u1.f;
        *(float2*)&outp[(size_t)(d0 + 2) * HW] = u2.f;
        *(float2*)&outp[(size_t)(d0 + 3) * HW] = u3.f;
    }
}

// 672 blocks, heavy-first: L3 [0,32) | L2 [32,160) | L1 [160,672).
// Each block: 256 px x 96 d (dhalf).
__global__ void __launch_bounds__(B_NT, 4)
conv_kernel(const float* __restrict__ w1, const float* __restrict__ b1,
            const float* __restrict__ w2, const float* __restrict__ b2,
            const float* __restrict__ w3, const float* __restrict__ b3,
            float* __restrict__ out)
{
    __shared__ __align__(16) u64 ws2[TOT_U64];
    const int tid = threadIdx.x;
    const int b = blockIdx.x;

    int pxblk, dhalf, lvl;
    const float *wsrc, *bsrc;
    if (b < 32)       { lvl = 2; pxblk = b >> 1;           dhalf = b & 1; wsrc = w3; bsrc = b3; }
    else if (b < 160) { lvl = 1; int q = b - 32;  pxblk = q >> 1; dhalf = q & 1; wsrc = w2; bsrc = b2; }
    else              { lvl = 0; int q = b - 160; pxblk = q >> 1; dhalf = q & 1; wsrc = w1; bsrc = b1; }

    // stage duplicated weights + bias: 2400 float2-units -> u64 pairs (STS.128)
#pragma unroll
    for (int j = 0; j < 19; j++) {
        int idx = tid + j * B_NT;
        if (j < 18 || idx < 2400) {
            if (idx < 2352) {
                int k = idx / 48, q = idx - k * 48;          // q covers 2 d
                float2 wv = *(const float2*)&wsrc[k * 192 + dhalf * 96 + 2 * q];
                ulonglong2 dup; dup.x = pk(wv.x, wv.x); dup.y = pk(wv.y, wv.y);
                *(ulonglong2*)&ws2[k * 96 + 2 * q] = dup;
            } else {
                int q = idx - 2352;                          // 0..47
                float2 bv = *(const float2*)&bsrc[dhalf * 96 + 2 * q];
                ulonglong2 dup; dup.x = pk(bv.x, bv.x); dup.y = pk(bv.y, bv.y);
                *(ulonglong2*)&ws2[WB_U64 + 2 * q] = dup;
            }
        }
    }

    // load corr px pair {px0,px1} (sum channel-parts for L2/L3) -> u64 regs
    const int p0 = pxblk * 256 + tid * 2;     // local px within level (even)
    u64 corrp[49];
    float* outp;
    if (lvl == 0) {
#pragma unroll
        for (int k = 0; k < 49; k++)
            corrp[k] = *(const u64*)&g_scratch[(size_t)k * SL + p0];
        int img = p0 >> 14, pix = p0 & 16383;
        outp = out + (size_t)img * 192 * 16384 + (size_t)dhalf * 96 * 16384 + pix;
    } else if (lvl == 1) {
#pragma unroll
        for (int k = 0; k < 49; k++) {
            u64 u = *(const u64*)&g_scratch[(size_t)k * SL + 65536 + p0];
            u64 v = *(const u64*)&g_scratch[(size_t)k * SL + 81920 + p0];
            corrp[k] = add2(u, v);
        }
        int img = p0 >> 12, pix = p0 & 4095;
        outp = out + 12582912u + (size_t)img * 192 * 4096 + (size_t)dhalf * 96 * 4096 + pix;
    } else {
#pragma unroll
        for (int k = 0; k < 49; k++) {
            u64 u = *(const u64*)&g_scratch[(size_t)k * SL +  98304 + p0];
            u64 v = *(const u64*)&g_scratch[(size_t)k * SL + 102400 + p0];
            u64 w = *(const u64*)&g_scratch[(size_t)k * SL + 106496 + p0];
            corrp[k] = add2(add2(u, v), w);
        }
        int img = p0 >> 10, pix = p0 & 1023;
        outp = out + 15728640u + (size_t)img * 192 * 1024 + (size_t)dhalf * 96 * 1024 + pix;
    }

    __syncthreads();

    if (lvl == 0)      conv_gemm<16384>(corrp, ws2, outp);
    else if (lvl == 1) conv_gemm<4096>(corrp, ws2, outp);
    else               conv_gemm<1024>(corrp, ws2, outp);
}

extern "C" void kernel_launch(void* const* d_in, const int* in_sizes, int n_in,
                              void* d_out, int out_size) {
    const float* l1 = (const float*)d_in[0];
    const float* l2 = (const float*)d_in[1];
    const float* l3 = (const float*)d_in[2];
    const float* w1 = (const float*)d_in[3];
    const float* b1 = (const float*)d_in[4];
    const float* w2 = (const float*)d_in[5];
    const float* b2 = (const float*)d_in[6];
    const float* w3 = (const float*)d_in[7];
    const float* b3 = (const float*)d_in[8];
    float* out = (float*)d_out;

    cudaFuncSetAttribute((const void*)corr_kernel,
                         cudaFuncAttributePreferredSharedMemoryCarveout, 100);
    cudaFuncSetAttribute((const void*)conv_kernel,
                         cudaFuncAttributePreferredSharedMemoryCarveout, 100);

    corr_kernel<<<432, A_NT>>>(l1, l2, l3);
    conv_kernel<<<672, B_NT>>>(w1, b1, w2, b2, w3, b3, out);
}

// round 13
// speedup vs baseline: 1.4015x; 1.4015x over previous
#include <cuda_runtime.h>

// Two-kernel pipeline:
//  A) corr_kernel: 49-offset wraparound correlation -> g_scratch[49][slots].
//     864 equal-work blocks (128 px x 64 ch). OFFSET-SPLIT warp specialization:
//     warps 0-1 (role A) compute iy 0..3 (28 offsets, halo rows tyr+3..6),
//     warps 2-3 (role B) compute iy 4..6 (21 offsets, halo rows tyr+0..2).
//     Halves the accumulator registers (56 max) -> 5 blocks/SM instead of 4.
//  B) conv_kernel: exact round-11 version (43.2us measured): corr[49] in float2
//     regs, broadcast weights in 19.2KB smem, 2px x 96d per thread, f32x2 FMA.

#define SL 110592   // 65536 (L1) + 2*16384 (L2 parts) + 3*4096 (L3 parts)
__device__ __align__(16) float g_scratch[49 * SL];

__device__ __forceinline__ void cp_async16(void* s, const void* g) {
    unsigned sa = (unsigned)__cvta_generic_to_shared(s);
    asm volatile("cp.async.ca.shared.global [%0], [%1], 16;\n" :: "r"(sa), "l"(g));
}
__device__ __forceinline__ void cp_commit() { asm volatile("cp.async.commit_group;\n" ::: "memory"); }
__device__ __forceinline__ void cp_wait0()  { asm volatile("cp.async.wait_group 0;\n" ::: "memory"); }
__device__ __forceinline__ void cp_wait1()  { asm volatile("cp.async.wait_group 1;\n" ::: "memory"); }

typedef unsigned long long u64;
__device__ __forceinline__ void ffma2(u64& d, u64 a, u64 b) {
    asm("fma.rn.f32x2 %0, %1, %2, %0;" : "+l"(d) : "l"(a), "l"(b));
}
__device__ __forceinline__ u64 pk(float lo, float hi) {
    u64 r;
    asm("mov.b64 %0, {%1, %2};" : "=l"(r) : "f"(lo), "f"(hi));
    return r;
}
union U2 { u64 u; float2 f; };

// ---------------- Kernel A: correlation, offset-split roles ----------------
#define A_NT 128
#define CC 4
#define F2W 40              // halo row: cols x0-4 .. x0+35 (float4-aligned)
#define F2H 10              // 4 tile rows + 6
#define NOFF (F2H * 10)     // 100 wrapped float4 offsets
#define F1C (CC*4*32)       // 512 floats
#define F2C (CC*F2H*F2W)    // 1600 floats
#define F2C4 (F2C/4)        // 400 float4
#define ABUF (F1C + F2C)    // 2112
#define NCH (64/CC)         // 16

// One role's full chunk loop. IY0/NIY select the offset rows this thread owns.
// Both instantiations contain the SAME barrier sequence (role-divergent
// warp-specialization; barriers are count-matched across the branch).
template<int IY0, int NIY, int H, int W>
__device__ __forceinline__ void corr_loop(
    const float* __restrict__ f1, const float* __restrict__ f2,
    int x0, int y0, int slot0, float scale, float* sbuf, const int* off2s)
{
    const int tid  = threadIdx.x;
    const int rtid = tid & 63;
    const int tx   = rtid & 15;     // 16 threads * 2px = 32-wide tile
    const int tyr  = rtid >> 4;     // 4 rows
    const int HW = H * W;

    const float* f1t = f1 + y0 * W + x0;
    auto prefetch = [&](int c0, float* buf) {
        {   // f1: 128 float4, one per thread
            int c = tid >> 5, rem = tid & 31;
            int r = rem >> 3, q = rem & 7;
            cp_async16(buf + tid * 4, f1t + (size_t)(c0 + c) * HW + r * W + q * 4);
        }
        float* f2b = buf + F1C;
#pragma unroll
        for (int j = 0; j < 4; j++) {            // f2: 400 float4
            int idx = tid + j * A_NT;
            if (j < 3 || idx < F2C4) {
                int c = idx / 100, rem = idx - c * 100;
                cp_async16(f2b + idx * 4, f2 + (size_t)(c0 + c) * HW + off2s[rem]);
            }
        }
        cp_commit();
    };

    u64 acc[NIY * 7];
#pragma unroll
    for (int k = 0; k < NIY * 7; k++) acc[k] = 0ull;

    prefetch(0, sbuf);
    prefetch(CC, sbuf + ABUF);

#pragma unroll 1
    for (int i = 0; i < NCH; i++) {
        if (i + 1 < NCH) cp_wait1(); else cp_wait0();
        __syncthreads();
        const float* buf = sbuf + (i & 1) * ABUF;
        const float* f1s = buf;
        const float* f2s = buf + F1C;
#pragma unroll
        for (int c = 0; c < CC; c++) {
            const float2 f1v = *(const float2*)&f1s[c * 128 + tyr * 32 + 2 * tx];
            const u64 f1p = pk(f1v.x, f1v.y);
            const float* f2c = f2s + c * (F2H * F2W);
#pragma unroll
            for (int ii = 0; ii < NIY; ii++) {
                const int iy = IY0 + ii;
                // dy = iy-3 -> halo row tyr+6-iy; taps for px pair (2tx+p):
                // halo col j = 2tx + p + 7 - ix  (halo starts at gmem col x0-4)
                const float2* row = (const float2*)(f2c + (tyr + 6 - iy) * F2W) + tx;
                float2 e0 = row[0], e1 = row[1], e2 = row[2], e3 = row[3], e4 = row[4];
                const int k0 = ii * 7;
                ffma2(acc[k0 + 0], f1p, pk(e3.y, e4.x));   // {7,8}
                ffma2(acc[k0 + 1], f1p, pk(e3.x, e3.y));   // {6,7}
                ffma2(acc[k0 + 2], f1p, pk(e2.y, e3.x));   // {5,6}
                ffma2(acc[k0 + 3], f1p, pk(e2.x, e2.y));   // {4,5}
                ffma2(acc[k0 + 4], f1p, pk(e1.y, e2.x));   // {3,4}
                ffma2(acc[k0 + 5], f1p, pk(e1.x, e1.y));   // {2,3}
                ffma2(acc[k0 + 6], f1p, pk(e0.y, e1.x));   // {1,2}
            }
        }
        __syncthreads();
        if (i + 2 < NCH) prefetch((i + 2) * CC, sbuf + (i & 1) * ABUF);
    }

    const int slot = slot0 + (y0 + tyr) * W + x0 + 2 * tx;
#pragma unroll
    for (int kk = 0; kk < NIY * 7; kk++) {
        U2 u; u.u = acc[kk];
        float2 v = make_float2(u.f.x * scale, u.f.y * scale);
        *(float2*)&g_scratch[(size_t)(IY0 * 7 + kk) * SL + slot] = v;
    }
}

template<int H, int W>
__device__ __forceinline__ void corr_block(
    const float* __restrict__ f1, const float* __restrict__ f2,
    int x0, int y0, int slot0, float scale, float* sbuf, int* off2s)
{
    const int tid = threadIdx.x;
    // per-(row, float4) wrapped gmem offsets for the f2 halo (channel-local)
    if (tid < NOFF) {
        int r = tid / 10, q = tid - r * 10;
        int gr = y0 + r - 3;     if (gr < 0) gr += H; if (gr >= H) gr -= H;
        int gc = x0 - 4 + q * 4; if (gc < 0) gc += W; if (gc >= W) gc -= W;
        off2s[tid] = gr * W + gc;
    }
    __syncthreads();

    if (tid < 64) corr_loop<0, 4, H, W>(f1, f2, x0, y0, slot0, scale, sbuf, off2s);
    else          corr_loop<4, 3, H, W>(f1, f2, x0, y0, slot0, scale, sbuf, off2s);
}

// 864 equal-work blocks (128px x 64ch): L1 512 | L2 256 (2 parts) | L3 96 (3 parts)
__global__ void __launch_bounds__(A_NT, 5)
corr_kernel(const float* __restrict__ l1, const float* __restrict__ l2,
            const float* __restrict__ l3)
{
    __shared__ __align__(16) float sbuf[2 * ABUF];
    __shared__ int off2s[NOFF];
    const int b = blockIdx.x;
    if (b < 512) {
        int img = b >> 7, t = b & 127;                  // 4x32 tiles of 32x4
        int x0 = (t & 3) * 32, y0 = (t >> 2) * 4;
        const float* f1 = l1 + (size_t)img * 64 * 16384;
        const float* f2 = l1 + (size_t)(img + 2) * 64 * 16384;
        corr_block<128, 128>(f1, f2, x0, y0, img * 16384, 0.125f, sbuf, off2s);
    } else if (b < 768) {
        int q = b - 512;
        int img = q >> 6, r = q & 63;
        int part = r >> 5, t = r & 31;                  // 2x16 tiles
        int x0 = (t & 1) * 32, y0 = (t >> 1) * 4;
        const float* f1 = l2 + ((size_t)img * 128 + part * 64) * 4096;
        const float* f2 = l2 + ((size_t)(img + 2) * 128 + part * 64) * 4096;
        corr_block<64, 64>(f1, f2, x0, y0, 65536 + part * 16384 + img * 4096,
                           0.08838834764831845f, sbuf, off2s);
    } else {
        int q = b - 768;
        int img = q / 24, r = q - img * 24;
        int part = r >> 3, t = r & 7;                   // 1x8 tiles
        int y0 = t * 4;
        const float* f1 = l3 + ((size_t)img * 192 + part * 64) * 1024;
        const float* f2 = l3 + ((size_t)(img + 2) * 192 + part * 64) * 1024;
        corr_block<32, 32>(f1, f2, 0, y0, 98304 + part * 4096 + img * 1024,
                           0.07216878364870323f, sbuf, off2s);
    }
}

// ---------------- Kernel B: 1x1 conv, EXACT round-11 version ----------------
#define B_NT 128
// smem: ws[49][96] + bias[96] = 4800 floats = 19.2KB (static)
#define BS_OFF 4704

template<int HW>
__device__ __forceinline__ void conv_gemm(const float2* __restrict__ corrp,
                                          const float* __restrict__ ws,
                                          float* __restrict__ outp)
{
#pragma unroll 1
    for (int pass = 0; pass < 24; pass++) {
        const int d0 = pass * 4;
        float2 bi01 = *(const float2*)&ws[BS_OFF + d0];
        float2 bi23 = *(const float2*)&ws[BS_OFF + d0 + 2];
        u64 A01 = pk(bi01.x, bi01.y);   // px0: {d0, d0+1}
        u64 A23 = pk(bi23.x, bi23.y);   // px0: {d0+2, d0+3}
        u64 B01 = A01, B23 = A23;       // px1
#pragma unroll
        for (int k = 0; k < 49; k++) {
            float4 wv = *(const float4*)&ws[k * 96 + d0];    // broadcast LDS.128
            u64 w01 = pk(wv.x, wv.y);
            u64 w23 = pk(wv.z, wv.w);
            float2 cc = corrp[k];
            u64 c0 = pk(cc.x, cc.x);
            u64 c1 = pk(cc.y, cc.y);
            ffma2(A01, c0, w01); ffma2(A23, c0, w23);
            ffma2(B01, c1, w01); ffma2(B23, c1, w23);
        }
        U2 a01, a23, b01, b23;
        a01.u = A01; a23.u = A23; b01.u = B01; b23.u = B23;
        *(float2*)&outp[(size_t)(d0 + 0) * HW] = make_float2(a01.f.x, b01.f.x);
        *(float2*)&outp[(size_t)(d0 + 1) * HW] = make_float2(a01.f.y, b01.f.y);
        *(float2*)&outp[(size_t)(d0 + 2) * HW] = make_float2(a23.f.x, b23.f.x);
        *(float2*)&outp[(size_t)(d0 + 3) * HW] = make_float2(a23.f.y, b23.f.y);
    }
}

// 672 blocks: (pxblk, dhalf) pairs. L1: 512 | L2: 128 | L3: 32
__global__ void __launch_bounds__(B_NT, 4)
conv_kernel(const float* __restrict__ w1, const float* __restrict__ b1,
            const float* __restrict__ w2, const float* __restrict__ b2,
            const float* __restrict__ w3, const float* __restrict__ b3,
            float* __restrict__ out)
{
    __shared__ __align__(16) float ws[49 * 96 + 96];
    const int tid = threadIdx.x;
    const int b = blockIdx.x;

    int pxblk, dhalf, lvl;
    const float *wsrc, *bsrc;
    if (b < 512)      { pxblk = b >> 1;          dhalf = b & 1; lvl = 0; wsrc = w1; bsrc = b1; }
    else if (b < 640) { int q = b - 512; pxblk = q >> 1; dhalf = q & 1; lvl = 1; wsrc = w2; bsrc = b2; }
    else              { int q = b - 640; pxblk = q >> 1; dhalf = q & 1; lvl = 2; wsrc = w3; bsrc = b3; }

    // stage this d-half of w (49 x 24 float4) + bias (24 float4)
#pragma unroll
    for (int j = 0; j < 10; j++) {
        int idx = tid + j * B_NT;
        if (j < 9 || idx < 1200) {
            if (idx < 1176) {
                int k = idx / 24, q = idx - k * 24;
                cp_async16(ws + k * 96 + q * 4, wsrc + k * 192 + dhalf * 96 + q * 4);
            } else {
                int q = idx - 1176;
                cp_async16(ws + BS_OFF + q * 4, bsrc + dhalf * 96 + q * 4);
            }
        }
    }
    cp_commit();

    // load corr px pair (sum channel-parts for L2/L3); overlaps cp.async
    const int p0 = pxblk * 256 + tid * 2;     // local px within level
    float2 corrp[49];
    float* outp;
    if (lvl == 0) {
#pragma unroll
        for (int k = 0; k < 49; k++)
            corrp[k] = *(const float2*)&g_scratch[(size_t)k * SL + p0];
        int img = p0 >> 14, pix = p0 & 16383;
        outp = out + (size_t)img * 192 * 16384 + (size_t)dhalf * 96 * 16384 + pix;
    } else if (lvl == 1) {
#pragma unroll
        for (int k = 0; k < 49; k++) {
            float2 u = *(const float2*)&g_scratch[(size_t)k * SL + 65536 + p0];
            float2 v = *(const float2*)&g_scratch[(size_t)k * SL + 81920 + p0];
            corrp[k] = make_float2(u.x + v.x, u.y + v.y);
        }
        int img = p0 >> 12, pix = p0 & 4095;
        outp = out + 12582912u + (size_t)img * 192 * 4096 + (size_t)dhalf * 96 * 4096 + pix;
    } else {
#pragma unroll
        for (int k = 0; k < 49; k++) {
            float2 u = *(const float2*)&g_scratch[(size_t)k * SL +  98304 + p0];
            float2 v = *(const float2*)&g_scratch[(size_t)k * SL + 102400 + p0];
            float2 w = *(const float2*)&g_scratch[(size_t)k * SL + 106496 + p0];
            corrp[k] = make_float2(u.x + v.x + w.x, u.y + v.y + w.y);
        }
        int img = p0 >> 10, pix = p0 & 1023;
        outp = out + 15728640u + (size_t)img * 192 * 1024 + (size_t)dhalf * 96 * 1024 + pix;
    }

    cp_wait0();
    __syncthreads();

    if (lvl == 0)      conv_gemm<16384>(corrp, ws, outp);
    else if (lvl == 1) conv_gemm<4096>(corrp, ws, outp);
    else               conv_gemm<1024>(corrp, ws, outp);
}

extern "C" void kernel_launch(void* const* d_in, const int* in_sizes, int n_in,
                              void* d_out, int out_size) {
    const float* l1 = (const float*)d_in[0];
    const float* l2 = (const float*)d_in[1];
    const float* l3 = (const float*)d_in[2];
    const float* w1 = (const float*)d_in[3];
    const float* b1 = (const float*)d_in[4];
    const float* w2 = (const float*)d_in[5];
    const float* b2 = (const float*)d_in[6];
    const float* w3 = (const float*)d_in[7];
    const float* b3 = (const float*)d_in[8];
    float* out = (float*)d_out;

    cudaFuncSetAttribute((const void*)corr_kernel,
                         cudaFuncAttributePreferredSharedMemoryCarveout, 100);
    cudaFuncSetAttribute((const void*)conv_kernel,
                         cudaFuncAttributePreferredSharedMemoryCarveout, 100);

    corr_kernel<<<864, A_NT>>>(l1, l2, l3);
    conv_kernel<<<672, B_NT>>>(w1, b1, w2, b2, w3, b3, out);
}